// round 3
// baseline (speedup 1.0000x reference)
#include <cuda_runtime.h>
#include <cuda_bf16.h>
#include <cstdint>

// Problem constants
#define BB 8
#define SS 4096           // WIDTH*WIDTH
#define EE 128
#define WIDTH 64
#define NEDGE 512         // 32 paths * 16 edges per batch
#define EDGES_PER_BLK 32  // 512/16 parts

// Scratch for hidden = A @ v (16 MB static device allocation)
__device__ float g_hidden[(size_t)BB * SS * EE];

// Dynamic smem layout (floats):
//  [0, 16384)            W tile (Wv or Wp), 64 KB
//  [16384, 20480)        row buffer 32 x 128, 16 KB
//  [20480, 20992)        src node ids (512)
//  [20992, 21504)        dst node ids (512)
//  [21504, 21536)        flags (32)
#define SM_W      0
#define SM_BUF    16384
#define SM_SRC    20480
#define SM_DST    20992
#define SM_FLAG   21504
#define SM_FLOATS 21536

// ---------------------------------------------------------------------------
// Fill attn region with bp broadcast
__global__ void fill_bp_kernel(float4* __restrict__ out, const float4* __restrict__ bp4) {
    unsigned tid = blockIdx.x * blockDim.x + threadIdx.x;
    out[tid] = bp4[tid & 31];
}

// ---------------------------------------------------------------------------
// Scatter adjacency ones into both A copies (runs AFTER the big memset).
__global__ void set_edges_kernel(float* __restrict__ A1, float* __restrict__ A2,
                                 const int* __restrict__ edges) {
    int b = blockIdx.x;
    int i = threadIdx.x;           // 0..511
    const int4 v = ((const int4*)(edges))[(size_t)b * NEDGE + i];
    int src = v.y * WIDTH + v.x;
    int dst = v.w * WIDTH + v.z;
    size_t off = ((size_t)b * SS + src) * SS + dst;
    A1[off] = 1.0f;
    A2[off] = 1.0f;
}

// ---------------------------------------------------------------------------
// Kernel1: accumulate hidden rows (deduped (src,dst) pairs).
// grid = BB*16 blocks, 256 threads, Wv staged in smem, 16 rows/thread.
__global__ __launch_bounds__(256, 1)
void accum_kernel(const float* __restrict__ values,
                  const float* __restrict__ Wv,
                  const float* __restrict__ bv,
                  const int* __restrict__ edges) {
    extern __shared__ float sm[];
    float* W_s   = sm + SM_W;
    float* buf   = sm + SM_BUF;
    int*   src_s = (int*)(sm + SM_SRC);
    int*   dst_s = (int*)(sm + SM_DST);
    int*   flag  = (int*)(sm + SM_FLAG);

    int b  = blockIdx.x >> 4;
    int lo = (blockIdx.x & 15) * EDGES_PER_BLK;
    int tid  = threadIdx.x;
    int e    = tid & 127;
    int half = tid >> 7;

    // Load edges for this batch, compute node ids
    const int4* eg = (const int4*)(edges + (size_t)b * NEDGE * 4);
    for (int t = tid; t < NEDGE; t += 256) {
        int4 v = eg[t];
        src_s[t] = v.y * WIDTH + v.x;
        dst_s[t] = v.w * WIDTH + v.z;
    }
    __syncthreads();

    // Dedupe (src,dst) pairs against all earlier edges of the batch
    if (tid < EDGES_PER_BLK) {
        int i = lo + tid;
        int si = src_s[i], di = dst_s[i];
        int d = 0;
        for (int j = 0; j < i; j++)
            if (src_s[j] == si && dst_s[j] == di) { d = 1; break; }
        flag[tid] = d;
    }

    // Cooperative load Wv -> smem
    {
        const float4* W4 = (const float4*)Wv;
        float4* Ws4 = (float4*)W_s;
        for (int t = tid; t < 4096; t += 256) Ws4[t] = W4[t];
    }
    __syncthreads();

    // Gather value rows for my (non-dup) edges
    for (int r = half; r < EDGES_PER_BLK; r += 2) {
        int i = lo + r;
        buf[r * EE + e] = flag[r] ? 0.0f
                                  : values[((size_t)b * SS + dst_s[i]) * EE + e];
    }
    __syncthreads();

    // Batched matvec: 16 rows per thread
    float acc[16];
    #pragma unroll
    for (int r = 0; r < 16; r++) acc[r] = 0.0f;
    for (int k = 0; k < EE; k++) {
        float w = W_s[k * EE + e];
        #pragma unroll
        for (int r = 0; r < 16; r++)
            acc[r] = fmaf(buf[(2 * r + half) * EE + k], w, acc[r]);
    }

    float bve = bv[e];
    #pragma unroll
    for (int r = 0; r < 16; r++) {
        int row = 2 * r + half;
        int i = lo + row;
        if (!flag[row])
            atomicAdd(&g_hidden[((size_t)b * SS + src_s[i]) * EE + e], acc[r] + bve);
    }
}

// ---------------------------------------------------------------------------
// Kernel2: attn[b,src,:] = hidden[b,src,:] @ Wp + bp for first-occurrence srcs.
__global__ __launch_bounds__(256, 1)
void out_kernel(float* __restrict__ attn,
                const float* __restrict__ Wp,
                const float* __restrict__ bp,
                const int* __restrict__ edges) {
    extern __shared__ float sm[];
    float* W_s   = sm + SM_W;
    float* buf   = sm + SM_BUF;
    int*   src_s = (int*)(sm + SM_SRC);
    int*   flag  = (int*)(sm + SM_FLAG);

    int b  = blockIdx.x >> 4;
    int lo = (blockIdx.x & 15) * EDGES_PER_BLK;
    int tid  = threadIdx.x;
    int e    = tid & 127;
    int half = tid >> 7;

    const int4* eg = (const int4*)(edges + (size_t)b * NEDGE * 4);
    for (int t = tid; t < NEDGE; t += 256) {
        int4 v = eg[t];
        src_s[t] = v.y * WIDTH + v.x;
    }
    __syncthreads();

    // first-occurrence-of-src flags (flag=1 -> earlier edge had same src, skip)
    if (tid < EDGES_PER_BLK) {
        int i = lo + tid;
        int si = src_s[i];
        int d = 0;
        for (int j = 0; j < i; j++)
            if (src_s[j] == si) { d = 1; break; }
        flag[tid] = d;
    }

    {
        const float4* W4 = (const float4*)Wp;
        float4* Ws4 = (float4*)W_s;
        for (int t = tid; t < 4096; t += 256) Ws4[t] = W4[t];
    }
    __syncthreads();

    for (int r = half; r < EDGES_PER_BLK; r += 2) {
        int i = lo + r;
        buf[r * EE + e] = flag[r] ? 0.0f
                                  : g_hidden[((size_t)b * SS + src_s[i]) * EE + e];
    }
    __syncthreads();

    float acc[16];
    #pragma unroll
    for (int r = 0; r < 16; r++) acc[r] = 0.0f;
    for (int k = 0; k < EE; k++) {
        float w = W_s[k * EE + e];
        #pragma unroll
        for (int r = 0; r < 16; r++)
            acc[r] = fmaf(buf[(2 * r + half) * EE + k], w, acc[r]);
    }

    float bpe = bp[e];
    #pragma unroll
    for (int r = 0; r < 16; r++) {
        int row = 2 * r + half;
        int i = lo + row;
        if (!flag[row])
            attn[((size_t)b * SS + src_s[i]) * EE + e] = acc[r] + bpe;
    }
}

// ---------------------------------------------------------------------------
extern "C" void kernel_launch(void* const* d_in, const int* in_sizes, int n_in,
                              void* d_out, int out_size) {
    (void)in_sizes; (void)n_in; (void)out_size;

    const float* values = (const float*)d_in[2];
    const int*   edges  = (const int*)  d_in[3];
    const float* Wv     = (const float*)d_in[8];
    const float* bv     = (const float*)d_in[9];
    const float* Wp     = (const float*)d_in[10];
    const float* bp     = (const float*)d_in[11];

    float* out  = (float*)d_out;
    float* attn = out;                                    // [B,S,E]
    float* A1   = out + (size_t)BB * SS * EE;             // [B,S,S]
    float* A2   = A1 + (size_t)BB * SS * SS;              // [B,S,S]

    // One-time resources (created on the eager correctness call, before capture)
    static cudaStream_t s2 = nullptr;
    static cudaEvent_t ev_fork = nullptr, ev_join = nullptr;
    if (!s2) {
        cudaStreamCreateWithFlags(&s2, cudaStreamNonBlocking);
        cudaEventCreateWithFlags(&ev_fork, cudaEventDisableTiming);
        cudaEventCreateWithFlags(&ev_join, cudaEventDisableTiming);
        cudaFuncSetAttribute(accum_kernel, cudaFuncAttributeMaxDynamicSharedMemorySize,
                             SM_FLOATS * sizeof(float));
        cudaFuncSetAttribute(out_kernel, cudaFuncAttributeMaxDynamicSharedMemorySize,
                             SM_FLOATS * sizeof(float));
    }

    void* hidden_ptr = nullptr;
    cudaGetSymbolAddress(&hidden_ptr, g_hidden);

    // Fork: s2 joins the capture via event wait
    cudaEventRecord(ev_fork, 0);
    cudaStreamWaitEvent(s2, ev_fork, 0);

    // ---- stream 0: big adjacency zero (1.073 GB) then scatter ones ----
    cudaMemsetAsync(A1, 0, 2ull * BB * SS * SS * sizeof(float), 0);
    set_edges_kernel<<<BB, NEDGE, 0, 0>>>(A1, A2, edges);

    // ---- stream 2 (overlapped with the big memset) ----
    cudaMemsetAsync(hidden_ptr, 0, (size_t)BB * SS * EE * sizeof(float), s2);
    {
        unsigned total4 = BB * SS * (EE / 4);             // 1,048,576 float4s
        fill_bp_kernel<<<total4 / 256, 256, 0, s2>>>((float4*)attn, (const float4*)bp);
    }
    accum_kernel<<<BB * 16, 256, SM_FLOATS * sizeof(float), s2>>>(values, Wv, bv, edges);
    out_kernel<<<BB * 16, 256, SM_FLOATS * sizeof(float), s2>>>(attn, Wp, bp, edges);

    // Join back to the capture stream
    cudaEventRecord(ev_join, s2);
    cudaStreamWaitEvent(0, ev_join, 0);
}

// round 7
// speedup vs baseline: 1.2233x; 1.2233x over previous
#include <cuda_runtime.h>
#include <cuda_bf16.h>
#include <cstdint>

// Problem constants
#define BB 8
#define SS 4096           // WIDTH*WIDTH
#define EE 128
#define WIDTH 64
#define NEDGE 512         // 32 paths * 16 edges per batch

// Scratch for hidden = A @ v (16 MB static device allocation)
__device__ float g_hidden[(size_t)BB * SS * EE];

// ---------------------------------------------------------------------------
// Fill attn region with bp broadcast: out[row*128 + e] = bp[e]
__global__ void fill_bp_kernel(float4* __restrict__ out, const float4* __restrict__ bp4) {
    unsigned tid = blockIdx.x * blockDim.x + threadIdx.x;   // 0 .. B*S*32-1
    out[tid] = bp4[tid & 31];
}

// ---------------------------------------------------------------------------
// Scatter adjacency ones into both A copies (after the big memset).
__global__ void set_edges_kernel(float* __restrict__ A1, float* __restrict__ A2,
                                 const int* __restrict__ edges) {
    int b = blockIdx.x;
    int i = threadIdx.x;           // 0..511
    const int4 v = ((const int4*)edges)[(size_t)b * NEDGE + i];
    int src = v.y * WIDTH + v.x;
    int dst = v.w * WIDTH + v.z;
    size_t off = ((size_t)b * SS + src) * SS + dst;
    A1[off] = 1.0f;
    A2[off] = 1.0f;
}

// ---------------------------------------------------------------------------
// Per unique edge (b, src, dst): hidden[b,src,:] += values[b,dst,:] @ Wv + bv
// One block (128 threads) per edge; dedupe against earlier identical edges.
__global__ void accum_hidden_kernel(const float* __restrict__ values,
                                    const float* __restrict__ Wv,
                                    const float* __restrict__ bv,
                                    const int* __restrict__ edges) {
    int b = blockIdx.y;
    int i = blockIdx.x;            // edge index 0..511
    const int* eb = edges + (size_t)b * NEDGE * 4;
    int src = eb[i * 4 + 1] * WIDTH + eb[i * 4 + 0];
    int dst = eb[i * 4 + 3] * WIDTH + eb[i * 4 + 2];
    int key = src * SS + dst;

    __shared__ int dup;
    if (threadIdx.x == 0) dup = 0;
    __syncthreads();
    for (int j = threadIdx.x; j < i; j += blockDim.x) {
        int s2 = eb[j * 4 + 1] * WIDTH + eb[j * 4 + 0];
        int d2 = eb[j * 4 + 3] * WIDTH + eb[j * 4 + 2];
        if (s2 * SS + d2 == key) dup = 1;   // benign race
    }
    __syncthreads();
    if (dup) return;

    __shared__ float vrow[EE];
    int e = threadIdx.x;
    vrow[e] = values[((size_t)b * SS + dst) * EE + e];
    __syncthreads();

    float acc = bv[e];
    #pragma unroll 16
    for (int k = 0; k < EE; k++) {
        acc = fmaf(vrow[k], Wv[k * EE + e], acc);
    }
    atomicAdd(&g_hidden[((size_t)b * SS + src) * EE + e], acc);
}

// ---------------------------------------------------------------------------
// For each edge src row: attn[b,src,:] = hidden[b,src,:] @ Wp + bp
// Duplicate src rows write identical values — benign.
__global__ void out_rows_kernel(float* __restrict__ attn,
                                const float* __restrict__ Wp,
                                const float* __restrict__ bp,
                                const int* __restrict__ edges) {
    int b = blockIdx.y;
    int i = blockIdx.x;
    const int* eb = edges + ((size_t)b * NEDGE + i) * 4;
    int src = eb[1] * WIDTH + eb[0];

    __shared__ float hrow[EE];
    int e = threadIdx.x;
    hrow[e] = g_hidden[((size_t)b * SS + src) * EE + e];
    __syncthreads();

    float acc = bp[e];
    #pragma unroll 16
    for (int k = 0; k < EE; k++) {
        acc = fmaf(hrow[k], Wp[k * EE + e], acc);
    }
    attn[((size_t)b * SS + src) * EE + e] = acc;
}

// ---------------------------------------------------------------------------
extern "C" void kernel_launch(void* const* d_in, const int* in_sizes, int n_in,
                              void* d_out, int out_size) {
    (void)in_sizes; (void)n_in; (void)out_size;

    const float* values = (const float*)d_in[2];
    const int*   edges  = (const int*)  d_in[3];
    const float* Wv     = (const float*)d_in[8];
    const float* bv     = (const float*)d_in[9];
    const float* Wp     = (const float*)d_in[10];
    const float* bp     = (const float*)d_in[11];

    float* out  = (float*)d_out;
    float* attn = out;                                    // [B,S,E]
    float* A1   = out + (size_t)BB * SS * EE;             // [B,S,S]
    float* A2   = A1 + (size_t)BB * SS * SS;              // [B,S,S]

    // One-time resources (created on the eager correctness call, before capture)
    static cudaStream_t s1 = nullptr, s2 = nullptr;
    static cudaEvent_t ev_fork = nullptr, ev_j1 = nullptr, ev_j2 = nullptr;
    if (!s1) {
        cudaStreamCreateWithFlags(&s1, cudaStreamNonBlocking);
        cudaStreamCreateWithFlags(&s2, cudaStreamNonBlocking);
        cudaEventCreateWithFlags(&ev_fork, cudaEventDisableTiming);
        cudaEventCreateWithFlags(&ev_j1, cudaEventDisableTiming);
        cudaEventCreateWithFlags(&ev_j2, cudaEventDisableTiming);
    }

    void* hidden_ptr = nullptr;
    cudaGetSymbolAddress(&hidden_ptr, g_hidden);

    // Fork both worker streams off the capture (legacy) stream.
    cudaEventRecord(ev_fork, 0);
    cudaStreamWaitEvent(s1, ev_fork, 0);
    cudaStreamWaitEvent(s2, ev_fork, 0);

    // ---- branch s1: big adjacency zero (1.073 GB) then scatter ones ----
    cudaMemsetAsync(A1, 0, 2ull * BB * SS * SS * sizeof(float), s1);
    set_edges_kernel<<<BB, NEDGE, 0, s1>>>(A1, A2, edges);

    // ---- branch s2: everything else (hides under the big memset) ----
    cudaMemsetAsync(hidden_ptr, 0, (size_t)BB * SS * EE * sizeof(float), s2);
    {
        unsigned total4 = BB * SS * (EE / 4);             // 1,048,576 float4s
        fill_bp_kernel<<<total4 / 256, 256, 0, s2>>>((float4*)attn, (const float4*)bp);
    }
    {
        dim3 grid(NEDGE, BB);
        accum_hidden_kernel<<<grid, EE, 0, s2>>>(values, Wv, bv, edges);
        out_rows_kernel<<<grid, EE, 0, s2>>>(attn, Wp, bp, edges);
    }

    // Join both branches back to the capture stream.
    cudaEventRecord(ev_j1, s1);
    cudaEventRecord(ev_j2, s2);
    cudaStreamWaitEvent(0, ev_j1, 0);
    cudaStreamWaitEvent(0, ev_j2, 0);
}